// round 16
// baseline (speedup 1.0000x reference)
#include <cuda_runtime.h>
#include <math.h>
#include <stdint.h>
#include <stddef.h>

// ---------------------------------------------------------------------------
// SpeechTopKDecoder beam-search decoder, T=64 steps.
// Build R16: tensor-core TF32 GEMMs (3x split product), renamed symbols vs
// prior two submissions to dodge any artifact-cache poisoning.
// Non-GEMM stages identical to the 18.0ms fp32 build.
// ---------------------------------------------------------------------------

#define Bb   16
#define Kb   3
#define Sx   512
#define Hx   1024
#define Cx   2000
#define Tx   64
#define NHx  4
#define DHx  256
#define BKx  48
#define NEGV (-1000000000.0f)
#define SOSv 1
#define EOSv 2

#define SPL 8
#define SPQ 32
#define SPG 16

// ------------------------------ device scratch ------------------------------
__device__ float g_kT [(size_t)Bb * NHx * DHx * Sx];
__device__ float g_vv [(size_t)Bb * NHx * Sx * DHx];
__device__ float g_h  [2 * BKx * Hx];
__device__ float g_c  [2 * BKx * Hx];
__device__ float g_hs [2 * BKx * Hx];
__device__ float g_cs [2 * BKx * Hx];
__device__ float g_gatesP[(size_t)SPL * BKx * 4096];
__device__ float g_qP [(size_t)SPQ * BKx * Hx];
__device__ float g_pP [(size_t)SPQ * BKx * Hx];
__device__ float g_gP [(size_t)SPG * BKx * 2048];
__device__ float g_ctx [BKx * Hx];
__device__ float g_out1[BKx * Hx];
__device__ float g_tanh[BKx * Hx];
__device__ float g_cand[BKx * Cx];
__device__ float g_score[BKx];
__device__ int   g_inp [BKx];

// ------------------------------ reductions ----------------------------------
__device__ __forceinline__ float wMax(float v) {
#pragma unroll
    for (int o = 16; o; o >>= 1) v = fmaxf(v, __shfl_xor_sync(0xffffffffu, v, o));
    return v;
}
__device__ __forceinline__ float wSum(float v) {
#pragma unroll
    for (int o = 16; o; o >>= 1) v += __shfl_xor_sync(0xffffffffu, v, o);
    return v;
}
__device__ __forceinline__ float bMax(float v, float* red, int tid) {
    v = wMax(v);
    if ((tid & 31) == 0) red[tid >> 5] = v;
    __syncthreads();
    float r = red[0];
#pragma unroll
    for (int w = 1; w < 8; w++) r = fmaxf(r, red[w]);
    __syncthreads();
    return r;
}
__device__ __forceinline__ float bSum(float v, float* red, int tid) {
    v = wSum(v);
    if ((tid & 31) == 0) red[tid >> 5] = v;
    __syncthreads();
    float r = red[0];
#pragma unroll
    for (int w = 1; w < 8; w++) r += red[w];
    __syncthreads();
    return r;
}
__device__ __forceinline__ float sigmf(float x) { return 1.0f / (1.0f + expf(-x)); }

// ------------------------------ tf32 helpers --------------------------------
struct TfPair { uint32_t hi, lo; };
__device__ __forceinline__ uint32_t to_tf32(float x) {
    uint32_t r;
    asm("cvt.rna.tf32.f32 %0, %1;" : "=r"(r) : "f"(x));
    return r;
}
__device__ __forceinline__ TfPair tf32_lohi(float x) {
    TfPair p;
    p.hi = to_tf32(x);
    p.lo = to_tf32(__fsub_rn(x, __uint_as_float(p.hi)));
    return p;
}

#define MMA_TF32(d, a0, a1, a2, a3, b0, b1)                                    \
    asm volatile(                                                              \
        "mma.sync.aligned.m16n8k8.row.col.f32.tf32.tf32.f32 "                  \
        "{%0,%1,%2,%3}, {%4,%5,%6,%7}, {%8,%9}, {%0,%1,%2,%3};"                \
        : "+f"((d)[0]), "+f"((d)[1]), "+f"((d)[2]), "+f"((d)[3])               \
        : "r"(a0), "r"(a1), "r"(a2), "r"(a3), "r"(b0), "r"(b1))

// ------------------------------ init ----------------------------------------
__global__ void init_state_kernel() {
    int idx = blockIdx.x * 256 + threadIdx.x;
    if (idx < 2 * BKx * Hx) { g_h[idx] = 0.0f; g_c[idx] = 0.0f; }
    if (idx < BKx) {
        g_score[idx] = (idx % Kb == 0) ? 0.0f : NEGV;
        g_inp[idx] = SOSv;
    }
}

// ------------------------------ K/V projection ------------------------------
__global__ void __launch_bounds__(256)
kv_project_kernel(const float* __restrict__ enc, const float* __restrict__ W,
                  const float* __restrict__ bias, int z) {
    __shared__ float As[16][132];
    __shared__ float Bs[16][132];
    const int tid = threadIdx.x;
    const int tx = tid & 15, ty = tid >> 4;
    const int n0 = blockIdx.x * 128;
    const int m0 = blockIdx.y * 128;

    const int ak4 = tid & 3,  am = tid >> 2;
    const int bn4 = tid & 31, bkk = tid >> 5;

    float4 aR[2], bR[2];
    float acc[8][8];
#pragma unroll
    for (int i = 0; i < 8; i++)
#pragma unroll
        for (int j = 0; j < 8; j++) acc[i][j] = 0.0f;

#define KV_LOAD(kb)                                                            \
    {                                                                          \
        aR[0] = *(const float4*)(enc + (size_t)(m0 + am) * Hx + (kb) + ak4*4); \
        aR[1] = *(const float4*)(enc + (size_t)(m0 + 64 + am) * Hx + (kb) + ak4*4); \
        bR[0] = *(const float4*)(W + (size_t)((kb) + bkk) * Hx + n0 + bn4*4);  \
        bR[1] = *(const float4*)(W + (size_t)((kb) + 8 + bkk) * Hx + n0 + bn4*4); \
    }
#define KV_STORE()                                                             \
    {                                                                          \
        float av0[4] = {aR[0].x, aR[0].y, aR[0].z, aR[0].w};                   \
        float av1[4] = {aR[1].x, aR[1].y, aR[1].z, aR[1].w};                   \
        _Pragma("unroll")                                                      \
        for (int j = 0; j < 4; j++) {                                          \
            As[ak4*4 + j][am]      = av0[j];                                   \
            As[ak4*4 + j][64 + am] = av1[j];                                   \
        }                                                                      \
        *(float4*)&Bs[bkk][bn4*4]     = bR[0];                                 \
        *(float4*)&Bs[8 + bkk][bn4*4] = bR[1];                                 \
    }

    KV_LOAD(0);
#pragma unroll 1
    for (int t = 0; t < Hx / 16; t++) {
        __syncthreads();
        KV_STORE();
        __syncthreads();
        if (t + 1 < Hx / 16) KV_LOAD((t + 1) * 16);
#pragma unroll 2
        for (int kk = 0; kk < 16; kk++) {
            float a[8], b[8];
#pragma unroll
            for (int r = 0; r < 8; r++) a[r] = As[kk][ty + 16 * r];
#pragma unroll
            for (int k = 0; k < 8; k++) b[k] = Bs[kk][tx + 16 * k];
#pragma unroll
            for (int r = 0; r < 8; r++)
#pragma unroll
                for (int k = 0; k < 8; k++) acc[r][k] = fmaf(a[r], b[k], acc[r][k]);
        }
    }

#pragma unroll
    for (int r = 0; r < 8; r++) {
        int gm = m0 + ty + 16 * r;
        int b = gm >> 9, s = gm & 511;
#pragma unroll
        for (int k = 0; k < 8; k++) {
            int col = n0 + tx + 16 * k;
            int h = col >> 8, d = col & 255;
            float v = acc[r][k] + bias[col];
            if (z == 0)
                g_kT[(((size_t)b * NHx + h) * DHx + d) * Sx + s] = v;
            else
                g_vv[(((size_t)b * NHx + h) * Sx + s) * DHx + d] = v;
        }
    }
#undef KV_LOAD
#undef KV_STORE
}

// ------------------------------ LSTM GEMM (tf32) ----------------------------
// C_part[sp] = A(48,Kslice) @ B^T, B row-major (4096,1024), two A/B pairs.
// grid (16 n-tiles, SPL), 256 threads; warp owns 48x32 output via m16n8k8.
__global__ void __launch_bounds__(256)
lstm_mm_tc(const float* __restrict__ A0, const int* __restrict__ aidx,
           const float* __restrict__ B0,
           const float* __restrict__ A1, const float* __restrict__ B1,
           int kPerSplit, float* __restrict__ Cpart) {
    const int tid = threadIdx.x;
    const int warp = tid >> 5, lane = tid & 31;
    const int g = lane >> 2, c = lane & 3;
    const int n0 = blockIdx.x * 256 + warp * 32;
    const int sp = blockIdx.y;
    const int k0 = sp * kPerSplit;

    float acc[3][4][4];
#pragma unroll
    for (int mi = 0; mi < 3; mi++)
#pragma unroll
        for (int nj = 0; nj < 4; nj++) {
            acc[mi][nj][0] = 0.0f; acc[mi][nj][1] = 0.0f;
            acc[mi][nj][2] = 0.0f; acc[mi][nj][3] = 0.0f;
        }

    int rowsDirect[6], rowsGather[6];
#pragma unroll
    for (int i = 0; i < 3; i++) {
        rowsDirect[2 * i]     = 16 * i + g;
        rowsDirect[2 * i + 1] = 16 * i + g + 8;
    }
#pragma unroll
    for (int j = 0; j < 6; j++)
        rowsGather[j] = (aidx != nullptr) ? aidx[rowsDirect[j]] : rowsDirect[j];

#pragma unroll 1
    for (int pair = 0; pair < 2; pair++) {
        const float* A = pair ? A1 : A0;
        const float* B = pair ? B1 : B0;
        const int* rows = pair ? rowsDirect : rowsGather;
#pragma unroll 1
        for (int ks = 0; ks < kPerSplit; ks += 8) {
            const int kb = k0 + ks;
            TfPair b0[4], b1[4];
#pragma unroll
            for (int nj = 0; nj < 4; nj++) {
                const float* bp = B + (size_t)(n0 + nj * 8 + g) * Hx + kb + c;
                b0[nj] = tf32_lohi(bp[0]);
                b1[nj] = tf32_lohi(bp[4]);
            }
#pragma unroll
            for (int mi = 0; mi < 3; mi++) {
                const float* r0 = A + (size_t)rows[2 * mi] * Hx + kb + c;
                const float* r1 = A + (size_t)rows[2 * mi + 1] * Hx + kb + c;
                TfPair a0 = tf32_lohi(r0[0]);
                TfPair a1 = tf32_lohi(r1[0]);
                TfPair a2 = tf32_lohi(r0[4]);
                TfPair a3 = tf32_lohi(r1[4]);
#pragma unroll
                for (int nj = 0; nj < 4; nj++) {
                    MMA_TF32(acc[mi][nj], a0.lo, a1.lo, a2.lo, a3.lo, b0[nj].hi, b1[nj].hi);
                    MMA_TF32(acc[mi][nj], a0.hi, a1.hi, a2.hi, a3.hi, b0[nj].lo, b1[nj].lo);
                    MMA_TF32(acc[mi][nj], a0.hi, a1.hi, a2.hi, a3.hi, b0[nj].hi, b1[nj].hi);
                }
            }
        }
    }

#pragma unroll
    for (int mi = 0; mi < 3; mi++) {
        int ra = 16 * mi + g, rb = ra + 8;
#pragma unroll
        for (int nj = 0; nj < 4; nj++) {
            float* p0 = Cpart + ((size_t)sp * 48 + ra) * 4096 + n0 + nj * 8 + 2 * c;
            float* p1 = Cpart + ((size_t)sp * 48 + rb) * 4096 + n0 + nj * 8 + 2 * c;
            p0[0] = acc[mi][nj][0]; p0[1] = acc[mi][nj][1];
            p1[0] = acc[mi][nj][2]; p1[1] = acc[mi][nj][3];
        }
    }
}

// ------------------------------ KN GEMM (tf32) ------------------------------
// C_part[sp] = A(48,Kslice) @ B, B row-major (1024, N).
__global__ void __launch_bounds__(256)
kn_mm_tc(const float* __restrict__ A, const float* __restrict__ B,
         int kPerSplit, int Nreal, int Nstride, float* __restrict__ Cpart) {
    const int tid = threadIdx.x;
    const int warp = tid >> 5, lane = tid & 31;
    const int g = lane >> 2, c = lane & 3;
    const int n0 = blockIdx.x * 256 + warp * 32;
    const int sp = blockIdx.y;
    const int k0 = sp * kPerSplit;

    float acc[3][4][4];
#pragma unroll
    for (int mi = 0; mi < 3; mi++)
#pragma unroll
        for (int nj = 0; nj < 4; nj++) {
            acc[mi][nj][0] = 0.0f; acc[mi][nj][1] = 0.0f;
            acc[mi][nj][2] = 0.0f; acc[mi][nj][3] = 0.0f;
        }

#pragma unroll 1
    for (int ks = 0; ks < kPerSplit; ks += 8) {
        const int kb = k0 + ks;
        TfPair b0[4], b1[4];
#pragma unroll
        for (int nj = 0; nj < 4; nj++) {
            int col = n0 + nj * 8 + g;
            float x0 = 0.0f, x1 = 0.0f;
            if (col < Nreal) {
                x0 = B[(size_t)(kb + c) * Nreal + col];
                x1 = B[(size_t)(kb + c + 4) * Nreal + col];
            }
            b0[nj] = tf32_lohi(x0);
            b1[nj] = tf32_lohi(x1);
        }
#pragma unroll
        for (int mi = 0; mi < 3; mi++) {
            const float* r0 = A + (size_t)(16 * mi + g) * Hx + kb + c;
            const float* r1 = A + (size_t)(16 * mi + g + 8) * Hx + kb + c;
            TfPair a0 = tf32_lohi(r0[0]);
            TfPair a1 = tf32_lohi(r1[0]);
            TfPair a2 = tf32_lohi(r0[4]);
            TfPair a3 = tf32_lohi(r1[4]);
#pragma unroll
            for (int nj = 0; nj < 4; nj++) {
                MMA_TF32(acc[mi][nj], a0.lo, a1.lo, a2.lo, a3.lo, b0[nj].hi, b1[nj].hi);
                MMA_TF32(acc[mi][nj], a0.hi, a1.hi, a2.hi, a3.hi, b0[nj].lo, b1[nj].lo);
                MMA_TF32(acc[mi][nj], a0.hi, a1.hi, a2.hi, a3.hi, b0[nj].hi, b1[nj].hi);
            }
        }
    }

#pragma unroll
    for (int mi = 0; mi < 3; mi++) {
        int ra = 16 * mi + g, rb = ra + 8;
#pragma unroll
        for (int nj = 0; nj < 4; nj++) {
            float* p0 = Cpart + ((size_t)sp * 48 + ra) * Nstride + n0 + nj * 8 + 2 * c;
            float* p1 = Cpart + ((size_t)sp * 48 + rb) * Nstride + n0 + nj * 8 + 2 * c;
            p0[0] = acc[mi][nj][0]; p0[1] = acc[mi][nj][1];
            p1[0] = acc[mi][nj][2]; p1[1] = acc[mi][nj][3];
        }
    }
}

// ------------------------------ LSTM pointwise ------------------------------
__global__ void lstm_cell_kernel(int layer, const float* __restrict__ bih,
                                 const float* __restrict__ bhh) {
    int idx = blockIdx.x * 256 + threadIdx.x;
    int bk = idx >> 10, n = idx & 1023;
    float iv = 0.f, fv = 0.f, gv = 0.f, ov = 0.f;
#pragma unroll
    for (int p = 0; p < SPL; p++) {
        const float* r = g_gatesP + ((size_t)p * BKx + bk) * 4096;
        iv += r[n]; fv += r[n + 1024]; gv += r[n + 2048]; ov += r[n + 3072];
    }
    iv += bih[n]        + bhh[n];
    fv += bih[n + 1024] + bhh[n + 1024];
    gv += bih[n + 2048] + bhh[n + 2048];
    ov += bih[n + 3072] + bhh[n + 3072];
    size_t off = ((size_t)layer * BKx + bk) * Hx + n;
    float cp = g_c[off];
    float cn = sigmf(fv) * cp + sigmf(iv) * tanhf(gv);
    float hn = sigmf(ov) * tanhf(cn);
    g_cs[off] = cn;
    g_hs[off] = hn;
}

// ------------------------------ attention -----------------------------------
__global__ void cross_attn_kernel(const float* __restrict__ bq) {
    const int b = blockIdx.x, h = blockIdx.y, tid = threadIdx.x;
    __shared__ float q[3][256];
    __shared__ float att[3][512];
    __shared__ float red[8];
    __shared__ float inv[3];

    for (int e = tid; e < 3 * 256; e += 256) {
        int kb = e >> 8, d = e & 255;
        int col = h * 256 + d, row = b * 3 + kb;
        float v = bq[col];
#pragma unroll
        for (int p = 0; p < SPQ; p++) v += g_qP[((size_t)p * BKx + row) * Hx + col];
        q[kb][d] = v;
    }
    __syncthreads();

    const float* kbase = g_kT + ((size_t)(b * NHx + h) * DHx) * Sx;
#pragma unroll
    for (int r = 0; r < 2; r++) {
        int s = tid + r * 256;
        float a0 = 0.f, a1 = 0.f, a2 = 0.f;
#pragma unroll 16
        for (int d = 0; d < 256; d++) {
            float kv = kbase[(size_t)d * Sx + s];
            a0 += q[0][d] * kv; a1 += q[1][d] * kv; a2 += q[2][d] * kv;
        }
        const float sc = 1.0f / 16.0f;
        att[0][s] = a0 * sc; att[1][s] = a1 * sc; att[2][s] = a2 * sc;
    }
    __syncthreads();

#pragma unroll
    for (int kb = 0; kb < 3; kb++) {
        float m = fmaxf(att[kb][tid], att[kb][tid + 256]);
        m = bMax(m, red, tid);
        float e0 = expf(att[kb][tid] - m);
        float e1 = expf(att[kb][tid + 256] - m);
        att[kb][tid] = e0; att[kb][tid + 256] = e1;
        __syncthreads();
        float s = bSum(e0 + e1, red, tid);
        if (tid == 0) inv[kb] = 1.0f / s;
    }
    __syncthreads();

    const int d = tid;
    const float* vbase = g_vv + ((size_t)(b * NHx + h) * Sx) * DHx + d;
    float c0 = 0.f, c1 = 0.f, c2 = 0.f;
#pragma unroll 16
    for (int s = 0; s < Sx; s++) {
        float v = vbase[(size_t)s * DHx];
        c0 += att[0][s] * v; c1 += att[1][s] * v; c2 += att[2][s] * v;
    }
    g_ctx[(size_t)(b * 3 + 0) * Hx + h * 256 + d] = c0 * inv[0];
    g_ctx[(size_t)(b * 3 + 1) * Hx + h * 256 + d] = c1 * inv[1];
    g_ctx[(size_t)(b * 3 + 2) * Hx + h * 256 + d] = c2 * inv[2];
}

// ------------------------------ layernorms ----------------------------------
__global__ void layernorm1_kernel(const float* __restrict__ g1, const float* __restrict__ b1) {
    const int bk = blockIdx.x, tid = threadIdx.x;
    __shared__ float y[Hx];
    __shared__ float red[8];
    float loc = 0.f;
#pragma unroll
    for (int j = 0; j < 4; j++) {
        int n = tid + j * 256;
        float v = g_ctx[(size_t)bk * Hx + n] + g_hs[((size_t)1 * BKx + bk) * Hx + n];
        y[n] = v; loc += v;
    }
    float mean = bSum(loc, red, tid) * (1.0f / Hx);
    float loc2 = 0.f;
#pragma unroll
    for (int j = 0; j < 4; j++) {
        int n = tid + j * 256;
        float d = y[n] - mean; loc2 += d * d;
    }
    float var = bSum(loc2, red, tid) * (1.0f / Hx);
    float w = rsqrtf(var + 1e-5f);
#pragma unroll
    for (int j = 0; j < 4; j++) {
        int n = tid + j * 256;
        g_out1[(size_t)bk * Hx + n] = (y[n] - mean) * w * g1[n] + b1[n];
    }
}

__global__ void layernorm2_kernel(const float* __restrict__ bp,
                                  const float* __restrict__ g2, const float* __restrict__ b2) {
    const int bk = blockIdx.x, tid = threadIdx.x;
    __shared__ float y[Hx];
    __shared__ float red[8];
    float loc = 0.f;
#pragma unroll
    for (int j = 0; j < 4; j++) {
        int n = tid + j * 256;
        float v = bp[n] + g_out1[(size_t)bk * Hx + n];
#pragma unroll
        for (int p = 0; p < SPQ; p++) v += g_pP[((size_t)p * BKx + bk) * Hx + n];
        y[n] = v; loc += v;
    }
    float mean = bSum(loc, red, tid) * (1.0f / Hx);
    float loc2 = 0.f;
#pragma unroll
    for (int j = 0; j < 4; j++) {
        int n = tid + j * 256;
        float d = y[n] - mean; loc2 += d * d;
    }
    float var = bSum(loc2, red, tid) * (1.0f / Hx);
    float w = rsqrtf(var + 1e-5f);
#pragma unroll
    for (int j = 0; j < 4; j++) {
        int n = tid + j * 256;
        g_tanh[(size_t)bk * Hx + n] = tanhf((y[n] - mean) * w * g2[n] + b2[n]);
    }
}

// ------------------------------ log-softmax ---------------------------------
__global__ void logsoftmax_kernel(float* __restrict__ out, int step) {
    const int bk = blockIdx.x, tid = threadIdx.x;
    __shared__ float sl[Cx];
    __shared__ float red[8];
    float m = -INFINITY;
    for (int c = tid; c < Cx; c += 256) {
        float v = 0.f;
#pragma unroll
        for (int p = 0; p < SPG; p++) v += g_gP[((size_t)p * BKx + bk) * 2048 + c];
        sl[c] = v;
        m = fmaxf(m, v);
    }
    float M = bMax(m, red, tid);
    float s = 0.f;
    for (int c = tid; c < Cx; c += 256) s += expf(sl[c] - M);
    float S = bSum(s, red, tid);
    float lse = logf(S);
    float sc = g_score[bk];
    for (int c = tid; c < Cx; c += 256) {
        float lp = sl[c] - M - lse;
        out[((size_t)step * BKx + bk) * Cx + c] = lp;
        g_cand[(size_t)bk * Cx + c] = sc + lp;
    }
}

// ---------------- single-pass top-3 + beam update + gather ------------------
__device__ __forceinline__ void keep3(float v, int j,
                                      float& v0, int& j0, float& v1, int& j1,
                                      float& v2, int& j2) {
    if (v > v0 || (v == v0 && j < j0)) {
        v2 = v1; j2 = j1; v1 = v0; j1 = j0; v0 = v; j0 = j;
    } else if (v > v1 || (v == v1 && j < j1)) {
        v2 = v1; j2 = j1; v1 = v; j1 = j;
    } else if (v > v2 || (v == v2 && j < j2)) {
        v2 = v; j2 = j;
    }
}

__global__ void beam_select_kernel() {
    const int b = blockIdx.x, tid = threadIdx.x;
    __shared__ float sv[8][3];
    __shared__ int si[8][3];
    __shared__ int chI[3];
    __shared__ float chV[3];

    float v0 = -INFINITY, v1 = -INFINITY, v2 = -INFINITY;
    int j0 = 0x7fffffff, j1 = 0x7fffffff, j2 = 0x7fffffff;
    for (int j = tid; j < Kb * Cx; j += 256) {
        float v = g_cand[(size_t)(b * Kb + j / Cx) * Cx + (j % Cx)];
        keep3(v, j, v0, j0, v1, j1, v2, j2);
    }
#pragma unroll
    for (int o = 16; o; o >>= 1) {
        float w0 = __shfl_xor_sync(0xffffffffu, v0, o);
        float w1 = __shfl_xor_sync(0xffffffffu, v1, o);
        float w2 = __shfl_xor_sync(0xffffffffu, v2, o);
        int k0 = __shfl_xor_sync(0xffffffffu, j0, o);
        int k1 = __shfl_xor_sync(0xffffffffu, j1, o);
        int k2 = __shfl_xor_sync(0xffffffffu, j2, o);
        keep3(w0, k0, v0, j0, v1, j1, v2, j2);
        keep3(w1, k1, v0, j0, v1, j1, v2, j2);
        keep3(w2, k2, v0, j0, v1, j1, v2, j2);
    }
    if ((tid & 31) == 0) {
        int w = tid >> 5;
        sv[w][0] = v0; sv[w][1] = v1; sv[w][2] = v2;
        si[w][0] = j0; si[w][1] = j1; si[w][2] = j2;
    }
    __syncthreads();
    if (tid == 0) {
        float f0 = -INFINITY, f1 = -INFINITY, f2 = -INFINITY;
        int g0 = 0x7fffffff, g1 = 0x7fffffff, g2 = 0x7fffffff;
#pragma unroll
        for (int w = 0; w < 8; w++)
#pragma unroll
            for (int e = 0; e < 3; e++)
                keep3(sv[w][e], si[w][e], f0, g0, f1, g1, f2, g2);
        chI[0] = g0; chV[0] = f0;
        chI[1] = g1; chV[1] = f1;
        chI[2] = g2; chV[2] = f2;
    }
    __syncthreads();

    if (tid < 3) {
        int j = chI[tid];
        float v = chV[tid];
        int sym = j % Cx;
        g_inp[b * Kb + tid] = sym;
        g_score[b * Kb + tid] = (sym == EOSv) ? NEGV : v;
    }
    __syncthreads();

#pragma unroll
    for (int kb = 0; kb < 3; kb++) {
        int src = b * Kb + chI[kb] / Cx;
        int dstBk = b * Kb + kb;
#pragma unroll
        for (int l = 0; l < 2; l++) {
            size_t dst = ((size_t)l * BKx + dstBk) * Hx;
            size_t so  = ((size_t)l * BKx + src) * Hx;
#pragma unroll
            for (int j = 0; j < 4; j++) {
                int n = tid + j * 256;
                g_h[dst + n] = g_hs[so + n];
                g_c[dst + n] = g_cs[so + n];
            }
        }
    }
}

// ------------------------------ host launcher -------------------------------
extern "C" void kernel_launch(void* const* d_in, const int* in_sizes, int n_in,
                              void* d_out, int out_size) {
    const float* enc  = (const float*)d_in[0];
    const float* emb  = (const float*)d_in[1];
    const float* w_ih = (const float*)d_in[2];
    const float* w_hh = (const float*)d_in[3];
    const float* b_ih = (const float*)d_in[4];
    const float* b_hh = (const float*)d_in[5];
    const float* wq   = (const float*)d_in[6];
    const float* bq   = (const float*)d_in[7];
    const float* wk   = (const float*)d_in[8];
    const float* bk_  = (const float*)d_in[9];
    const float* wv   = (const float*)d_in[10];
    const float* bv   = (const float*)d_in[11];
    const float* ln1g = (const float*)d_in[12];
    const float* ln1b = (const float*)d_in[13];
    const float* wp   = (const float*)d_in[14];
    const float* bp   = (const float*)d_in[15];
    const float* ln2g = (const float*)d_in[16];
    const float* ln2b = (const float*)d_in[17];
    const float* wg   = (const float*)d_in[18];
    float* out = (float*)d_out;

    float *p_h, *p_hs, *p_out1, *p_tanh, *p_gatesP, *p_qP, *p_pP, *p_gP;
    int* p_inp;
    cudaGetSymbolAddress((void**)&p_h, g_h);
    cudaGetSymbolAddress((void**)&p_hs, g_hs);
    cudaGetSymbolAddress((void**)&p_out1, g_out1);
    cudaGetSymbolAddress((void**)&p_tanh, g_tanh);
    cudaGetSymbolAddress((void**)&p_gatesP, g_gatesP);
    cudaGetSymbolAddress((void**)&p_qP, g_qP);
    cudaGetSymbolAddress((void**)&p_pP, g_pP);
    cudaGetSymbolAddress((void**)&p_gP, g_gP);
    cudaGetSymbolAddress((void**)&p_inp, g_inp);

    init_state_kernel<<<384, 256>>>();
    kv_project_kernel<<<dim3(8, 64), 256>>>(enc, wk, bk_, 0);
    kv_project_kernel<<<dim3(8, 64), 256>>>(enc, wv, bv, 1);

    const size_t WL = (size_t)4096 * Hx;

    for (int t = 0; t < Tx; t++) {
        lstm_mm_tc<<<dim3(16, SPL), 256>>>(emb, p_inp, w_ih,
                                           p_h, w_hh, Hx / SPL, p_gatesP);
        lstm_cell_kernel<<<192, 256>>>(0, b_ih, b_hh);
        lstm_mm_tc<<<dim3(16, SPL), 256>>>(p_hs, nullptr, w_ih + WL,
                                           p_h + BKx * Hx, w_hh + WL,
                                           Hx / SPL, p_gatesP);
        lstm_cell_kernel<<<192, 256>>>(1, b_ih + 4096, b_hh + 4096);
        kn_mm_tc<<<dim3(4, SPQ), 256>>>(p_hs + BKx * Hx, wq, Hx / SPQ, Hx, Hx, p_qP);
        cross_attn_kernel<<<dim3(16, 4), 256>>>(bq);
        layernorm1_kernel<<<48, 256>>>(ln1g, ln1b);
        kn_mm_tc<<<dim3(4, SPQ), 256>>>(p_out1, wp, Hx / SPQ, Hx, Hx, p_pP);
        layernorm2_kernel<<<48, 256>>>(bp, ln2g, ln2b);
        kn_mm_tc<<<dim3(8, SPG), 256>>>(p_tanh, wg, Hx / SPG, Cx, 2048, p_gP);
        logsoftmax_kernel<<<48, 256>>>(out, t);
        beam_select_kernel<<<16, 256>>>();
    }
    (void)in_sizes; (void)n_in; (void)out_size;
}